// round 17
// baseline (speedup 1.0000x reference)
#include <cuda_runtime.h>
#include <cuda_fp16.h>
#include <cstdint>

// SparseLinearV: y = scatter(W_coo) @ x + bias
// Round 17: R16 (433.8us, tensor 61.0%, L1 50.8%) — the non-amortizing part
// of the loop cost is shared-pipe issue (96 LDS.64/warp/ktile). New gmem
// permutation packs each thread's fragments for TWO ks-steps into one 16B
// line (per 32-k chunk: c*8 + g*4 + pos), so fragment loads become LDS.128:
// 24 per warp per ktile instead of 48 LDS.64. AST=96 halves (stride 48
// words == 16 mod 32) keeps quarter-warp phases conflict-free for .128.
// BK=64 / 2-stage / 1-barrier structure unchanged from R16.

#define IN_F   4096
#define OUT_F  4096
#define NCOLS  4096

__device__ __half g_Wh [(size_t)IN_F * OUT_F];   // W (M x K), k-permuted fp16
__device__ __half g_XTh[(size_t)NCOLS * OUT_F];  // x^T (N x K), k-permuted fp16

// ---------------------------------------------------------------------------
// helpers
// ---------------------------------------------------------------------------
__device__ __forceinline__ void cp_async16(uint32_t smem_dst, const void* gsrc) {
    asm volatile("cp.async.cg.shared.global [%0], [%1], 16;" :: "r"(smem_dst), "l"(gsrc));
}
__device__ __forceinline__ void cp_commit() { asm volatile("cp.async.commit_group;"); }
template<int N> __device__ __forceinline__ void cp_wait() {
    asm volatile("cp.async.wait_group %0;" :: "n"(N) : "memory");
}
__device__ __forceinline__ uint32_t smem_u32(const void* p) {
    uint32_t a;
    asm("{ .reg .u64 t; cvta.to.shared.u64 t, %1; cvt.u32.u64 %0, t; }" : "=r"(a) : "l"(p));
    return a;
}
__device__ __forceinline__ void mma_f16(float c[4], unsigned a0, unsigned a1,
                                        unsigned a2, unsigned a3,
                                        unsigned b0, unsigned b1) {
    asm volatile(
        "mma.sync.aligned.m16n8k16.row.col.f32.f16.f16.f32 "
        "{%0,%1,%2,%3}, {%4,%5,%6,%7}, {%8,%9}, {%0,%1,%2,%3};"
        : "+f"(c[0]), "+f"(c[1]), "+f"(c[2]), "+f"(c[3])
        : "r"(a0), "r"(a1), "r"(a2), "r"(a3), "r"(b0), "r"(b1));
}
__device__ __forceinline__ uint32_t h2u(__half2 h) {
    return *reinterpret_cast<uint32_t*>(&h);
}

// ---------------------------------------------------------------------------
// Preprocessing
// ---------------------------------------------------------------------------
__global__ void zero_Wh_kernel() {
    size_t n8 = (size_t)IN_F * OUT_F / 8;
    uint4 z = make_uint4(0u, 0u, 0u, 0u);
    uint4* p = reinterpret_cast<uint4*>(g_Wh);
    for (size_t i = (size_t)blockIdx.x * blockDim.x + threadIdx.x;
         i < n8; i += (size_t)gridDim.x * blockDim.x)
        p[i] = z;
}

// COO scatter into fp16, NEW 32-k-chunk permutation applied in the address:
//   within a 32-group: g = (k>>4)&1, s = k&15
//   s<8:  c = s>>1,      pos = s&1
//   s>=8: c = (s-8)>>1,  pos = 2 + (s&1)
//   dst  = (k & ~31) + c*8 + g*4 + pos
__global__ void scatter_half_kernel(const int* __restrict__ rows,
                                    const int* __restrict__ cols,
                                    const float* __restrict__ vals, int nnz) {
    int i = blockIdx.x * blockDim.x + threadIdx.x;
    if (i < nnz) {
        const int k = cols[i];
        const int g = (k >> 4) & 1;
        const int s = k & 15;
        const int c = (s < 8) ? (s >> 1) : ((s - 8) >> 1);
        const int pos = (s < 8) ? (s & 1) : (2 + (s & 1));
        const size_t idx = (size_t)rows[i] * OUT_F + (k & ~31) + c * 8 + g * 4 + pos;
        atomicAdd(&g_Wh[idx], __float2half(vals[i]));
    }
}

// x (K x N) fp32 row-major -> g_XTh (N x K) fp16 row-major, chunk-permuted.
// Thread (grp, q4) writes quad {2q4,2q4+1, 2q4+8,2q4+9} of 16-group grp
// at offset q4*8 + grp*4 within its 32-chunk.
__global__ void transpose_convert_perm_kernel(const float* __restrict__ x) {
    __shared__ float t[32][33];
    const int bx = blockIdx.x * 32;  // n base
    const int by = blockIdx.y * 32;  // k base
    const int tx = threadIdx.x, ty = threadIdx.y;
#pragma unroll
    for (int i = 0; i < 4; i++)
        t[ty + 8 * i][tx] = x[(size_t)(by + ty + 8 * i) * NCOLS + bx + tx];
    __syncthreads();
    const int qc = tx & 7;
    const int nl = (tx >> 3) * 8 + ty;
    const int grp = qc >> 2;
    const int q4  = qc & 3;
    const int s0 = grp * 16 + 2 * q4;
    const int s2 = s0 + 8;
    uint2 out;
    out.x = h2u(__floats2half2_rn(t[s0][nl], t[s0 + 1][nl]));
    out.y = h2u(__floats2half2_rn(t[s2][nl], t[s2 + 1][nl]));
    *reinterpret_cast<uint2*>(&g_XTh[(size_t)(bx + nl) * OUT_F + by + q4 * 8 + grp * 4]) = out;
}

// ---------------------------------------------------------------------------
// GEMM: C(4096x4096) = W @ x + bias  (A = g_Wh, B = g_XTh, both K-major fp16)
//   BM=128, BN=128, BK=64, 256 threads, warp tile 64x32.
//   2-stage cp.async pipeline, ONE __syncthreads per ktile (64 iterations).
//   Fragment loads are LDS.128 (two ks-steps per load).
// ---------------------------------------------------------------------------
#define BM 128
#define BN 128
#define BK 64
#define NT (OUT_F / BK)            // 64
#define NSTAGE 2
#define AST 96                     // halves per smem row (64 data + 32 pad)
#define TILE_HALVES (BM * AST)     // 12288 halves = 24576 B
#define STAGE_HALVES (2 * TILE_HALVES)          // A + B tile = 49152 B
#define SMEM_TOTAL (NSTAGE * STAGE_HALVES * 2)  // 98304 B

__global__ __launch_bounds__(256, 2)
void gemm_f16_kernel(const float* __restrict__ bias, float* __restrict__ C) {
    extern __shared__ __align__(16) __half smem[];

    const int tid  = threadIdx.x;
    const int lane = tid & 31;
    const int wid  = tid >> 5;
    const int wm   = wid & 1;         // 0..1  (M direction, 64 rows)
    const int wn   = wid >> 1;        // 0..3  (N direction, 32 cols)
    const int r    = lane >> 2;       // 0..7
    const int c    = lane & 3;        // 0..3
    const int c2   = c * 2;           // epilogue col pair

    const int rowBase = blockIdx.y * BM;
    const int colBase = blockIdx.x * BN;

    uint32_t sA[NSTAGE], sB[NSTAGE];
#pragma unroll
    for (int s = 0; s < NSTAGE; s++) {
        sA[s] = smem_u32(smem + s * STAGE_HALVES);
        sB[s] = sA[s] + TILE_HALVES * 2;   // bytes
    }

    // Loader: 16B chunk = 8 halves. A tile: 128 rows x 8 chunks = 1024 chunks,
    // 4 per thread; B likewise. One commit_group per stage.
    auto load_stage = [&](int s, int k0) {
#pragma unroll
        for (int l = 0; l < 4; l++) {
            const int ch  = tid + 256 * l;
            const int row = ch >> 3;
            const int c16 = ch & 7;
            cp_async16(sA[s] + (uint32_t)(row * AST + c16 * 8) * 2,
                       &g_Wh[(size_t)(rowBase + row) * OUT_F + k0 + c16 * 8]);
        }
#pragma unroll
        for (int l = 0; l < 4; l++) {
            const int ch  = tid + 256 * l;
            const int row = ch >> 3;
            const int c16 = ch & 7;
            cp_async16(sB[s] + (uint32_t)(row * AST + c16 * 8) * 2,
                       &g_XTh[(size_t)(colBase + row) * OUT_F + k0 + c16 * 8]);
        }
        cp_commit();
    };

    float acc[4][4][4];
#pragma unroll
    for (int i = 0; i < 4; i++)
#pragma unroll
        for (int j = 0; j < 4; j++)
#pragma unroll
            for (int q = 0; q < 4; q++) acc[i][j][q] = 0.f;

    // Prologue: prefetch tile 0.
    load_stage(0, 0);

    for (int t = 0; t < NT; t++) {
        const int cur = t & 1;
        cp_wait<0>();                  // tile t resident
        __syncthreads();               // all warps done with stage (t-1)&1

        if (t + 1 < NT) load_stage(cur ^ 1, (t + 1) * BK);

        const __half* Ab = reinterpret_cast<const __half*>(smem) + cur * STAGE_HALVES;
        const __half* Bb = Ab + TILE_HALVES;
#pragma unroll
        for (int h = 0; h < 2; h++) {          // 32-k chunk; covers ks=2h, 2h+1
            const int kh = h * 32 + c * 8;
            uint4 a0[4], a1[4], bq[4];
#pragma unroll
            for (int i = 0; i < 4; i++) {
                const int m = wm * 64 + i * 16 + r;
                a0[i] = *reinterpret_cast<const uint4*>(&Ab[m * AST + kh]);
                a1[i] = *reinterpret_cast<const uint4*>(&Ab[(m + 8) * AST + kh]);
            }
#pragma unroll
            for (int j = 0; j < 4; j++) {
                const int n = wn * 32 + j * 8 + r;
                bq[j] = *reinterpret_cast<const uint4*>(&Bb[n * AST + kh]);
            }
            // ks = 2h (16-group g0): .x/.y words
#pragma unroll
            for (int i = 0; i < 4; i++)
#pragma unroll
                for (int j = 0; j < 4; j++)
                    mma_f16(acc[i][j], a0[i].x, a1[i].x, a0[i].y, a1[i].y,
                            bq[j].x, bq[j].y);
            // ks = 2h+1 (16-group g1): .z/.w words
#pragma unroll
            for (int i = 0; i < 4; i++)
#pragma unroll
                for (int j = 0; j < 4; j++)
                    mma_f16(acc[i][j], a0[i].z, a1[i].z, a0[i].w, a1[i].w,
                            bq[j].z, bq[j].w);
        }
    }

    // Epilogue: bias add + float2 stores.
    float2 bv[4];
#pragma unroll
    for (int j = 0; j < 4; j++)
        bv[j] = *reinterpret_cast<const float2*>(&bias[colBase + wn * 32 + j * 8 + c2]);
#pragma unroll
    for (int i = 0; i < 4; i++) {
        const int row0 = rowBase + wm * 64 + i * 16 + r;
#pragma unroll
        for (int j = 0; j < 4; j++) {
            const int col = colBase + wn * 32 + j * 8 + c2;
            float2 o0 = make_float2(acc[i][j][0] + bv[j].x, acc[i][j][1] + bv[j].y);
            float2 o1 = make_float2(acc[i][j][2] + bv[j].x, acc[i][j][3] + bv[j].y);
            *reinterpret_cast<float2*>(&C[(size_t)row0 * NCOLS + col])       = o0;
            *reinterpret_cast<float2*>(&C[(size_t)(row0 + 8) * NCOLS + col]) = o1;
        }
    }
}

// ---------------------------------------------------------------------------
// Launch
// ---------------------------------------------------------------------------
extern "C" void kernel_launch(void* const* d_in, const int* in_sizes, int n_in,
                              void* d_out, int out_size) {
    const float* x    = (const float*)d_in[0];
    const int*   rows = (const int*)d_in[1];
    const int*   cols = (const int*)d_in[2];
    const float* vals = (const float*)d_in[3];
    const float* bias = (const float*)d_in[4];
    float*       y    = (float*)d_out;
    const int nnz = in_sizes[1];

    cudaFuncSetAttribute(gemm_f16_kernel,
                         cudaFuncAttributeMaxDynamicSharedMemorySize, SMEM_TOTAL);

    zero_Wh_kernel<<<1184, 256>>>();
    scatter_half_kernel<<<(nnz + 255) / 256, 256>>>(rows, cols, vals, nnz);
    transpose_convert_perm_kernel<<<dim3(NCOLS / 32, OUT_F / 32), dim3(32, 8)>>>(x);

    dim3 grid(NCOLS / BN, IN_F / BM);  // 32 x 32 = 1024 CTAs
    gemm_f16_kernel<<<grid, 256, SMEM_TOTAL>>>(bias, y);
}